// round 7
// baseline (speedup 1.0000x reference)
#include <cuda_runtime.h>
#include <math.h>

#define HW 4096
#define NTILES 640
#define NHALF  1280
#define NTOT_F 2621440.0f
#define EPS_V 1e-8f

#define SPARSITY_W 0.8f
#define CONC_W     1.5f
#define COORD_W    1.0f
#define BG_W       0.1f

__device__ float g_part[NHALF][10];
__device__ float g_tile_contrib[NTILES];
__device__ unsigned int g_tile_cnt[NTILES];   // zero-init; reset by consumer
__device__ unsigned int g_done = 0;

__device__ __forceinline__ float fast_tanh(float x) {
    float r;
    asm("tanh.approx.f32 %0, %1;" : "=f"(r) : "f"(x));
    return r;
}

// One CTA per HALF tile (32 rows): 128 threads, 16 px/thread.
// grid 1280, 9 CTAs/SM -> whole grid resident in one wave, 12.5% imbalance.
__global__ __launch_bounds__(128, 9)
void loss_kernel(const float4* __restrict__ pred,
                 const float4* __restrict__ tgt,
                 float* __restrict__ out) {
    __shared__ float warp_red[4][10];
    __shared__ bool is_last;

    const int hidx = blockIdx.x;           // [0,1280)
    const int tile = hidx >> 1;
    const int half = hidx & 1;
    const size_t base = (size_t)tile * (HW / 4) + (size_t)half * 512;

    const int tid  = threadIdx.x;          // [0,128)
    const int lane = tid & 31;
    const int wid  = tid >> 5;             // [0,4)

    // elem j (within tile) = half*2048 + 4*(tid + 128k) + c
    //   col = ((4*tid)&63) + c           (k-invariant)
    //   row = 32*half + (tid>>4) + 8k
    const float c0f = (float)((tid * 4) & 63);
    const float y0f = (float)((tid >> 4) + 32 * half);

    const float4* __restrict__ P = pred + base;
    const float4* __restrict__ T = tgt  + base;

    float S = 0.f, Ts = 0.f;
    float wxp = 0.f, wyp = 0.f, wxt = 0.f, wyt = 0.f;
    float foc = 0.f, bg = 0.f, plog = 0.f, mxh = -0.5f;

    const unsigned FULL = 0xffffffffu;

    // depth-2 pipeline over 4 (pred,tgt) float4 pairs
    float4 xc = P[tid];
    float4 tc = T[tid];

    #pragma unroll
    for (int k = 0; k < 4; k++) {
        float4 xn, tn;
        if (k < 3) { xn = P[tid + 128 * (k + 1)]; tn = T[tid + 128 * (k + 1)]; }

        float xv[4] = {xc.x, xc.y, xc.z, xc.w};
        float tv[4] = {tc.x, tc.y, tc.z, tc.w};
        float pv[4], lpv[4];

        // common math (target-independent)
        #pragma unroll
        for (int c = 0; c < 4; c++) {
            float x  = xv[c];
            float h  = 0.5f * fast_tanh(0.5f * x);  // p - 0.5
            float p  = h + 0.5f;
            float pm = 0.5f + fabsf(h);             // sigmoid(|x|)
            float lp = __logf(pm);                  // -lp = log1p(e^{-|x|})
            pv[c]  = p;
            lpv[c] = lp;
            plog = fmaf(p, fminf(x, 0.f) + lp, plog);   // p*log(p)
            mxh  = fmaxf(mxh, h);
        }
        const float kf = (float)k;
        float gs = (pv[0] + pv[1]) + (pv[2] + pv[3]);
        float gw = fmaf(3.f, pv[3], fmaf(2.f, pv[2], pv[1]));
        S   += gs;
        wxp += gw;
        wyp  = fmaf(kf, gs, wyp);

        // sparse-target fast path: ~88% of groups have t==0 across the warp
        float tsum = (tv[0] + tv[1]) + (tv[2] + tv[3]);
        if (__ballot_sync(FULL, tsum != 0.f)) {
            #pragma unroll
            for (int c = 0; c < 4; c++) {
                float t    = tv[c];
                float p    = pv[c];
                float bce0 = fmaxf(xv[c], 0.f) - lpv[c];
                float bce  = fmaf(-xv[c], t, bce0);
                float om   = fabsf(t - p);
                float om2  = om * om;
                foc = fmaf(om2, bce, foc);
                bg  = fmaf(om2, 1.f - t, bg);
            }
            float gt = tsum;
            float gu = fmaf(3.f, tv[3], fmaf(2.f, tv[2], tv[1]));
            Ts  += gt;
            wxt += gu;
            wyt  = fmaf(kf, gt, wyt);
        } else {
            #pragma unroll
            for (int c = 0; c < 4; c++) {
                float p    = pv[c];
                float p2   = p * p;
                float bce0 = fmaxf(xv[c], 0.f) - lpv[c];
                foc = fmaf(p2, bce0, foc);
                bg += p2;
            }
        }
        xc = xn; tc = tn;
    }

    float pxs = fmaf(c0f, S,  wxp);
    float pys = fmaf(y0f, S,  8.f * wyp);   // rows step by 8 per k
    float txs = fmaf(c0f, Ts, wxt);
    float tys = fmaf(y0f, Ts, 8.f * wyt);
    float mx  = mxh + 0.5f;

    // warp butterfly: 9 sums + 1 max
    #pragma unroll
    for (int o = 16; o; o >>= 1) {
        S    += __shfl_xor_sync(FULL, S,    o);
        Ts   += __shfl_xor_sync(FULL, Ts,   o);
        pxs  += __shfl_xor_sync(FULL, pxs,  o);
        pys  += __shfl_xor_sync(FULL, pys,  o);
        txs  += __shfl_xor_sync(FULL, txs,  o);
        tys  += __shfl_xor_sync(FULL, tys,  o);
        foc  += __shfl_xor_sync(FULL, foc,  o);
        bg   += __shfl_xor_sync(FULL, bg,   o);
        plog += __shfl_xor_sync(FULL, plog, o);
        mx    = fmaxf(mx, __shfl_xor_sync(FULL, mx, o));
    }
    if (lane == 0) {
        warp_red[wid][0] = S;    warp_red[wid][1] = Ts;
        warp_red[wid][2] = pxs;  warp_red[wid][3] = pys;
        warp_red[wid][4] = txs;  warp_red[wid][5] = tys;
        warp_red[wid][6] = foc;  warp_red[wid][7] = bg;
        warp_red[wid][8] = plog; warp_red[wid][9] = mx;
    }
    __syncthreads();

    // cross-warp combine: 4 lanes of warp 0
    if (wid == 0 && lane < 4) {
        float a[10];
        #pragma unroll
        for (int i = 0; i < 10; i++) a[i] = warp_red[lane][i];
        const unsigned M4 = 0x0000000fu;
        #pragma unroll
        for (int o = 2; o; o >>= 1) {
            #pragma unroll
            for (int i = 0; i < 9; i++) a[i] += __shfl_xor_sync(M4, a[i], o);
            a[9] = fmaxf(a[9], __shfl_xor_sync(M4, a[9], o));
        }
        if (lane == 0) {
            #pragma unroll
            for (int i = 0; i < 10; i++) g_part[hidx][i] = a[i];
            __threadfence();
            unsigned r = atomicAdd(&g_tile_cnt[tile], 1u);
            bool last = false;
            if (r == 1) {
                __threadfence();
                const int other = hidx ^ 1;
                float b[10];
                #pragma unroll
                for (int i = 0; i < 10; i++) b[i] = g_part[other][i];
                #pragma unroll
                for (int i = 0; i < 9; i++) a[i] += b[i];   // commutative -> deterministic
                a[9] = fmaxf(a[9], b[9]);

                float Sp  = a[0] + EPS_V;
                float inv = 1.f / Sp;
                float ent = inv * (a[0] * logf(Sp) - a[8]);
                float ts  = a[1] + EPS_V;
                float px  = a[2] * inv, py = a[3] * inv;
                float tx  = a[4] / ts,  ty = a[5] / ts;
                float dx  = px - tx,    dy = py - ty;
                float coord = sqrtf(dx * dx + dy * dy);
                float conc  = 1.f - a[9];

                g_tile_contrib[tile] =
                    (a[6] + BG_W * a[7]) * (1.f / NTOT_F) +
                    (SPARSITY_W * ent + CONC_W * conc + COORD_W * coord) * (1.f / (float)NTILES);

                g_tile_cnt[tile] = 0;      // reset for graph replay
                __threadfence();
                unsigned d = atomicAdd(&g_done, 1u);
                last = (d == NTILES - 1);
            }
            is_last = last;
        }
    }
    __syncthreads();

    if (is_last) {
        __threadfence();
        float v = 0.f;
        #pragma unroll
        for (int i = 0; i < 5; i++)               // 640 / 128
            v += g_tile_contrib[tid + 128 * i];
        #pragma unroll
        for (int o = 16; o; o >>= 1)
            v += __shfl_xor_sync(FULL, v, o);
        if (lane == 0) warp_red[wid][0] = v;
        __syncthreads();
        if (tid == 0) {
            float s = (warp_red[0][0] + warp_red[1][0])
                    + (warp_red[2][0] + warp_red[3][0]);
            out[0] = s;
            g_done = 0;   // reset for graph replay
        }
    }
}

extern "C" void kernel_launch(void* const* d_in, const int* in_sizes, int n_in,
                              void* d_out, int out_size) {
    const float4* pred = (const float4*)d_in[0];
    const float4* tgt  = (const float4*)d_in[1];
    float* out = (float*)d_out;
    loss_kernel<<<NHALF, 128>>>(pred, tgt, out);
}

// round 8
// speedup vs baseline: 1.1875x; 1.1875x over previous
#include <cuda_runtime.h>
#include <math.h>

#define HW 4096
#define NTILES 640
#define NTOT_F 2621440.0f
#define EPS_V 1e-8f

#define SPARSITY_W 0.8f
#define CONC_W     1.5f
#define COORD_W    1.0f
#define BG_W       0.1f

__device__ float g_tile_contrib[NTILES];
__device__ unsigned int g_done = 0;

__device__ __forceinline__ float fast_tanh(float x) {
    float r;
    asm("tanh.approx.f32 %0, %1;" : "=f"(r) : "f"(x));
    return r;
}

// One CTA per tile: 128 threads, 32 px/thread (8 float4 pairs, all loads
// front-issued -> MLP=16). grid 640 x 4 warps: fully resident in one wave.
__global__ __launch_bounds__(128, 5)
void loss_kernel(const float4* __restrict__ pred,
                 const float4* __restrict__ tgt,
                 float* __restrict__ out) {
    __shared__ float warp_red[4][10];
    __shared__ bool is_last;

    const int tile = blockIdx.x;
    const float4* __restrict__ P = pred + (size_t)tile * (HW / 4);
    const float4* __restrict__ T = tgt  + (size_t)tile * (HW / 4);

    const int tid  = threadIdx.x;          // [0,128)
    const int lane = tid & 31;
    const int wid  = tid >> 5;             // [0,4)

    // elem j = 4*(tid + 128k) + c, k=0..7:
    //   col = ((4*tid)&63) + c   (k-invariant)
    //   row = (tid>>4) + 8k
    const float c0f = (float)((tid * 4) & 63);
    const float y0f = (float)(tid >> 4);

    // front-load everything (16 x LDG.128 in flight)
    float4 X[8], Tv4[8];
    #pragma unroll
    for (int k = 0; k < 8; k++) X[k]   = P[tid + 128 * k];
    #pragma unroll
    for (int k = 0; k < 8; k++) Tv4[k] = T[tid + 128 * k];

    float S = 0.f, Ts = 0.f;
    float wxp = 0.f, wyp = 0.f, wxt = 0.f, wyt = 0.f;
    float foc = 0.f, bg = 0.f, plog = 0.f, mxh = -0.5f;

    #pragma unroll
    for (int k = 0; k < 8; k++) {
        float xv[4] = {X[k].x,   X[k].y,   X[k].z,   X[k].w};
        float tv[4] = {Tv4[k].x, Tv4[k].y, Tv4[k].z, Tv4[k].w};
        float pv[4];
        #pragma unroll
        for (int c = 0; c < 4; c++) {
            float x  = xv[c];
            float t  = tv[c];
            float h  = 0.5f * fast_tanh(0.5f * x);  // p - 0.5
            float p  = h + 0.5f;
            pv[c] = p;
            float pm = 0.5f + fabsf(h);             // sigmoid(|x|)
            float lp = __logf(pm);                  // -lp = log1p(e^{-|x|})
            float bce = fmaf(-x, t, fmaxf(x, 0.f) - lp);
            float om  = fabsf(t - p);               // 1 - p_t (t in {0,1})
            float om2 = om * om;
            foc  = fmaf(om2, bce, foc);
            bg   = fmaf(om2, 1.f - t, bg);          // p^2 when t==0
            plog = fmaf(p, fminf(x, 0.f) + lp, plog);
            mxh  = fmaxf(mxh, h);
        }
        const float kf = (float)k;
        float gs = (pv[0] + pv[1]) + (pv[2] + pv[3]);
        float gw = fmaf(3.f, pv[3], fmaf(2.f, pv[2], pv[1]));
        S   += gs;
        wxp += gw;
        wyp  = fmaf(kf, gs, wyp);
        float gt = (tv[0] + tv[1]) + (tv[2] + tv[3]);
        float gu = fmaf(3.f, tv[3], fmaf(2.f, tv[2], tv[1]));
        Ts  += gt;
        wxt += gu;
        wyt  = fmaf(kf, gt, wyt);
    }

    float pxs = fmaf(c0f, S,  wxp);
    float pys = fmaf(y0f, S,  8.f * wyp);    // rows step by 8 per k
    float txs = fmaf(c0f, Ts, wxt);
    float tys = fmaf(y0f, Ts, 8.f * wyt);
    float mx  = mxh + 0.5f;

    // warp butterfly: 9 sums + 1 max
    const unsigned FULL = 0xffffffffu;
    #pragma unroll
    for (int o = 16; o; o >>= 1) {
        S    += __shfl_xor_sync(FULL, S,    o);
        Ts   += __shfl_xor_sync(FULL, Ts,   o);
        pxs  += __shfl_xor_sync(FULL, pxs,  o);
        pys  += __shfl_xor_sync(FULL, pys,  o);
        txs  += __shfl_xor_sync(FULL, txs,  o);
        tys  += __shfl_xor_sync(FULL, tys,  o);
        foc  += __shfl_xor_sync(FULL, foc,  o);
        bg   += __shfl_xor_sync(FULL, bg,   o);
        plog += __shfl_xor_sync(FULL, plog, o);
        mx    = fmaxf(mx, __shfl_xor_sync(FULL, mx, o));
    }
    if (lane == 0) {
        warp_red[wid][0] = S;    warp_red[wid][1] = Ts;
        warp_red[wid][2] = pxs;  warp_red[wid][3] = pys;
        warp_red[wid][4] = txs;  warp_red[wid][5] = tys;
        warp_red[wid][6] = foc;  warp_red[wid][7] = bg;
        warp_red[wid][8] = plog; warp_red[wid][9] = mx;
    }
    __syncthreads();

    // cross-warp combine: 4 lanes of warp 0
    if (wid == 0 && lane < 4) {
        float a[10];
        #pragma unroll
        for (int i = 0; i < 10; i++) a[i] = warp_red[lane][i];
        const unsigned M4 = 0x0000000fu;
        #pragma unroll
        for (int o = 2; o; o >>= 1) {
            #pragma unroll
            for (int i = 0; i < 9; i++) a[i] += __shfl_xor_sync(M4, a[i], o);
            a[9] = fmaxf(a[9], __shfl_xor_sync(M4, a[9], o));
        }
        if (lane == 0) {
            float Sp  = a[0] + EPS_V;
            float inv = 1.f / Sp;
            float ent = inv * (a[0] * logf(Sp) - a[8]);
            float ts  = a[1] + EPS_V;
            float px  = a[2] * inv, py = a[3] * inv;
            float tx  = a[4] / ts,  ty = a[5] / ts;
            float dx  = px - tx,    dy = py - ty;
            float coord = sqrtf(dx * dx + dy * dy);
            float conc  = 1.f - a[9];

            g_tile_contrib[tile] =
                (a[6] + BG_W * a[7]) * (1.f / NTOT_F) +
                (SPARSITY_W * ent + CONC_W * conc + COORD_W * coord) * (1.f / (float)NTILES);

            __threadfence();
            unsigned r = atomicAdd(&g_done, 1u);
            is_last = (r == NTILES - 1);
        }
    }
    __syncthreads();

    if (is_last) {
        __threadfence();
        float v = 0.f;
        #pragma unroll
        for (int i = 0; i < 5; i++)                // 640 / 128
            v += g_tile_contrib[tid + 128 * i];
        #pragma unroll
        for (int o = 16; o; o >>= 1)
            v += __shfl_xor_sync(FULL, v, o);
        if (lane == 0) warp_red[wid][0] = v;
        __syncthreads();
        if (tid == 0) {
            float s = (warp_red[0][0] + warp_red[1][0])
                    + (warp_red[2][0] + warp_red[3][0]);
            out[0] = s;
            g_done = 0;   // reset for graph replay
        }
    }
}

extern "C" void kernel_launch(void* const* d_in, const int* in_sizes, int n_in,
                              void* d_out, int out_size) {
    const float4* pred = (const float4*)d_in[0];
    const float4* tgt  = (const float4*)d_in[1];
    float* out = (float*)d_out;
    loss_kernel<<<NTILES, 128>>>(pred, tgt, out);
}